// round 1
// baseline (speedup 1.0000x reference)
#include <cuda_runtime.h>
#include <cuda_bf16.h>
#include <math.h>

typedef unsigned long long ull;

// ---------------- scratch (device globals; no allocation allowed) ----------
__device__ float g_kern[32 * 4 * 9 * 64];   // [b][w][pos][c] pooled kernels
__device__ float g_kk[32 * 9 * 64];         // [b][pos][c] effective dw kernel
__device__ float g_pwt[64 * 64];            // po_w transposed: [c][o]

// ---------------- helpers ---------------------------------------------------
__device__ __forceinline__ float gelu_exact(float x) {
    return 0.5f * x * (1.0f + erff(x * 0.70710678118654752440f));
}
__device__ __forceinline__ float sigm(float x) { return 1.0f / (1.0f + expf(-x)); }

__device__ __forceinline__ ull pack2(float lo, float hi) {
    ull r; asm("mov.b64 %0, {%1, %2};" : "=l"(r) : "f"(lo), "f"(hi)); return r;
}
__device__ __forceinline__ void fma2(ull& d, ull a, ull b) {
    asm("fma.rn.f32x2 %0, %1, %2, %0;" : "+l"(d) : "l"(a), "l"(b));
}
__device__ __forceinline__ float2 unpack2(ull v) {
    float2 r; asm("mov.b64 {%0, %1}, %2;" : "=f"(r.x), "=f"(r.y) : "l"(v)); return r;
}
__device__ __forceinline__ float4 ldg4(const float* p) {
    return __ldg((const float4*)p);
}

// ---------------- kernel 1: adaptive avg pool 48x48 -> 3x3 ------------------
// grid = 128 (b*4 + w), block = 768 (48 rows x 16 channel-quads)
__global__ void pool_kernel(const float* __restrict__ x) {
    __shared__ float4 part[48 * 3 * 16];   // [r][j][q]
    const int t = threadIdx.x;
    const int bw = blockIdx.x;
    const int b = bw >> 2, w = bw & 3;
    const int r = t >> 4, q = t & 15;
    const int wh0 = (w >> 1) * 48, ww0 = (w & 1) * 48;

    const float* xp = x + ((size_t)b * 9216 + (size_t)(wh0 + r) * 96 + ww0) * 64 + q * 4;

    #pragma unroll
    for (int j = 0; j < 3; j++) {
        float4 acc = make_float4(0.f, 0.f, 0.f, 0.f);
        #pragma unroll 4
        for (int cc = 0; cc < 16; cc++) {
            float4 v = ldg4(xp + (size_t)(j * 16 + cc) * 64);
            acc.x += v.x; acc.y += v.y; acc.z += v.z; acc.w += v.w;
        }
        part[(r * 3 + j) * 16 + q] = acc;
    }
    __syncthreads();

    if (t < 144) {
        const int q2 = t & 15, pos = t >> 4;
        const int i = pos / 3, j = pos - i * 3;
        float4 s = make_float4(0.f, 0.f, 0.f, 0.f);
        #pragma unroll
        for (int rr = 0; rr < 16; rr++) {
            float4 v = part[((i * 16 + rr) * 3 + j) * 16 + q2];
            s.x += v.x; s.y += v.y; s.z += v.z; s.w += v.w;
        }
        const float sc = 1.0f / 256.0f;
        s.x *= sc; s.y *= sc; s.z *= sc; s.w *= sc;
        *(float4*)&g_kern[((size_t)(b * 4 + w) * 9 + pos) * 64 + q2 * 4] = s;
    }
}

// ---------------- kernel T: transpose po_w ----------------------------------
__global__ void transpose_pw(const float* __restrict__ po_w) {
    const int t = threadIdx.x;
    for (int i = t; i < 4096; i += 256) {
        int o = i >> 6, c = i & 63;
        g_pwt[c * 64 + o] = __ldg(&po_w[i]);
    }
}

// ---------------- kernel 2: per-batch "brain" -> effective kernel kk --------
// grid = 32 (batch), block = 256, dynamic smem 54352 B
__global__ void k2_kernel(
    const float* __restrict__ se_w1, const float* __restrict__ se_b1,
    const float* __restrict__ se_w2, const float* __restrict__ se_b2,
    const float* __restrict__ dc_w,  const float* __restrict__ dc_b,
    const float* __restrict__ l1_w,  const float* __restrict__ l1_b,
    const float* __restrict__ l2_w,  const float* __restrict__ l2_b,
    const float* __restrict__ gkf_w, const float* __restrict__ gkf_b,
    const float* __restrict__ fu_proj_w, const float* __restrict__ fu_proj_b,
    const float* __restrict__ fu_fc1_w,  const float* __restrict__ fu_fc1_b,
    const float* __restrict__ fu_fc2_w,  const float* __restrict__ fu_fc2_b,
    const float* __restrict__ fu_po_w,   const float* __restrict__ fu_po_b)
{
    extern __shared__ float sm[];
    float* s_kern = sm;              // 2304  [w][pos][c]
    float* s_h1   = sm + 2304;       // 2304
    float* s_se   = sm + 4608;       // 2304  kern_se
    float* s_w    = sm + 6912;       // 4160  (64 rows, stride 65)
    float* s_gkf  = sm + 11072;      // 576   [pos][c]
    float* s_xsum = sm + 11648;      // 576   [pos][c]
    float* s_wm   = sm + 12224;      // 256   winmean [w][c]
    float* s_v0   = sm + 12480;      // 256
    float* s_red  = sm + 12736;      // 256
    float* s_v    = sm + 12992;      // 64
    float* s_log  = sm + 13056;      // 256
    float* s_av   = sm + 13312;      // 256
    float* s_l1   = sm + 13568;      // 16
    float* s_ww   = sm + 13584;      // 4

    const int t = threadIdx.x;
    const int b = blockIdx.x;

    // P0: load pooled kernels + se_w1 (padded)
    for (int i = t; i < 2304; i += 256) s_kern[i] = g_kern[b * 2304 + i];
    for (int i = t; i < 4096; i += 256) s_w[(i >> 6) * 65 + (i & 63)] = __ldg(&se_w1[i]);
    __syncthreads();

    // P1: SE layer 1 (gelu)
    #pragma unroll 1
    for (int k = 0; k < 9; k++) {
        const int out = t + 256 * k;
        const int c = out & 63, wp = out >> 6;
        float acc = __ldg(&se_b1[c]);
        const float* wr = &s_w[c * 65];
        const float* kr = &s_kern[wp * 64];
        #pragma unroll 8
        for (int ci = 0; ci < 64; ci++) acc = fmaf(wr[ci], kr[ci], acc);
        s_h1[wp * 64 + c] = gelu_exact(acc);
    }
    __syncthreads();
    for (int i = t; i < 4096; i += 256) s_w[(i >> 6) * 65 + (i & 63)] = __ldg(&se_w2[i]);
    __syncthreads();

    // P3: SE layer 2 (sigmoid) + window means
    #pragma unroll 1
    for (int k = 0; k < 9; k++) {
        const int out = t + 256 * k;
        const int c = out & 63, wp = out >> 6;
        float acc = __ldg(&se_b2[c]);
        const float* wr = &s_w[c * 65];
        const float* hr = &s_h1[wp * 64];
        #pragma unroll 8
        for (int ci = 0; ci < 64; ci++) acc = fmaf(wr[ci], hr[ci], acc);
        s_se[wp * 64 + c] = sigm(acc);
    }
    {
        const int w_ = t >> 6, c = t & 63;
        float s = 0.f;
        #pragma unroll
        for (int pos = 0; pos < 9; pos++) s += s_kern[w_ * 576 + pos * 64 + c];
        s_wm[t] = s * (1.0f / 9.0f);
    }
    __syncthreads();

    // P4: fusion proj + gelu + GAP -> v0   (thread = (g,o))
    {
        const int g = t >> 2, o = t & 3;
        const int wwin = g >> 4;
        float wreg[4];
        #pragma unroll
        for (int i = 0; i < 4; i++) wreg[i] = __ldg(&fu_proj_w[g * 16 + o * 4 + i]);
        const float bb = __ldg(&fu_proj_b[g * 4 + o]);
        float vs = 0.f;
        #pragma unroll
        for (int pos = 0; pos < 9; pos++) {
            float s = bb;
            #pragma unroll
            for (int i = 0; i < 4; i++) {
                const int c = ((g & 15) << 2) + i;
                s = fmaf(wreg[i], s_se[wwin * 576 + pos * 64 + c], s);
            }
            vs += gelu_exact(s);
        }
        s_v0[t] = vs * (1.0f / 9.0f);
    }
    __syncthreads();

    // P5: window reweight chain (warp 0)
    if (t < 32) {
        if (t < 4) {
            float a = __ldg(&dc_b[t]);
            for (int c = 0; c < 64; c++) a = fmaf(__ldg(&dc_w[t * 64 + c]), s_wm[t * 64 + c], a);
            s_ww[t] = a;
        }
        __syncwarp();
        if (t < 16) {
            float a = __ldg(&l1_b[t]);
            #pragma unroll
            for (int w = 0; w < 4; w++) a = fmaf(__ldg(&l1_w[t * 4 + w]), s_ww[w], a);
            s_l1[t] = gelu_exact(a);
        }
        __syncwarp();
        if (t < 4) {
            float a = __ldg(&l2_b[t]);
            #pragma unroll
            for (int j = 0; j < 16; j++) a = fmaf(__ldg(&l2_w[t * 16 + j]), s_l1[j], a);
            s_ww[t] = sigm(a);
        }
    }
    __syncthreads();

    // P6: fc1 (256 -> 64) with 4-way k split
    {
        const int c = t & 63, part = t >> 6;
        float acc = 0.f;
        const float* wp = &fu_fc1_w[c * 256 + part * 64];
        const float* vp = &s_v0[part * 64];
        #pragma unroll 4
        for (int kk = 0; kk < 16; kk++) {
            float4 a = ldg4(wp + kk * 4);
            float4 v4 = *(const float4*)(vp + kk * 4);
            acc += a.x * v4.x + a.y * v4.y + a.z * v4.z + a.w * v4.w;
        }
        s_red[t] = acc;
    }
    __syncthreads();
    if (t < 64)
        s_v[t] = gelu_exact(__ldg(&fu_fc1_b[t]) + s_red[t] + s_red[t + 64] + s_red[t + 128] + s_red[t + 192]);
    __syncthreads();

    // P7: fc2 logits (64 -> 256)
    {
        float acc = __ldg(&fu_fc2_b[t]);
        const float* wp = &fu_fc2_w[t * 64];
        #pragma unroll 4
        for (int kk = 0; kk < 16; kk++) {
            float4 a = ldg4(wp + kk * 4);
            float4 v4 = *(const float4*)&s_v[kk * 4];
            acc += a.x * v4.x + a.y * v4.y + a.z * v4.z + a.w * v4.w;
        }
        s_log[t] = acc;
    }
    __syncthreads();

    // P8: softmax over windows (per c), then gkf
    if (t < 64) {
        float m = s_log[t];
        #pragma unroll
        for (int w = 1; w < 4; w++) m = fmaxf(m, s_log[w * 64 + t]);
        float e[4]; float den = 0.f;
        #pragma unroll
        for (int w = 0; w < 4; w++) { e[w] = expf(s_log[w * 64 + t] - m); den += e[w]; }
        const float inv = 1.0f / den;
        #pragma unroll
        for (int w = 0; w < 4; w++) s_av[w * 64 + t] = e[w] * inv;
    }
    __syncthreads();

    #pragma unroll 1
    for (int k = 0; k < 3; k++) {
        const int out = t + 256 * k;
        if (out < 576) {
            const int c = out & 63, pos = out >> 6;
            float a = __ldg(&gkf_b[c]);
            float xsum = 0.f;
            #pragma unroll
            for (int w = 0; w < 4; w++) {
                const float se = s_se[w * 576 + pos * 64 + c];
                a = fmaf(__ldg(&gkf_w[c * 4 + w]) * s_ww[w], se, a);
                xsum = fmaf(s_av[w * 64 + c], se, xsum);
            }
            s_gkf[pos * 64 + c] = a;
            s_xsum[pos * 64 + c] = xsum;
        }
    }
    for (int i = t; i < 4096; i += 256) s_w[(i >> 6) * 65 + (i & 63)] = __ldg(&fu_po_w[i]);
    __syncthreads();

    // P10: gks_extra = fu_po(x_sum); kk = 2*gkf + gks_extra
    #pragma unroll 1
    for (int k = 0; k < 3; k++) {
        const int out = t + 256 * k;
        if (out < 576) {
            const int c = out & 63, pos = out >> 6;
            float a = __ldg(&fu_po_b[c]);
            const float* wr = &s_w[c * 65];
            const float* xr = &s_xsum[pos * 64];
            #pragma unroll 8
            for (int ci = 0; ci < 64; ci++) a = fmaf(wr[ci], xr[ci], a);
            g_kk[b * 576 + pos * 64 + c] = 2.0f * s_gkf[pos * 64 + c] + a;
        }
    }
}

// ---------------- kernel 3: fused depthwise 3x3 + pointwise 64x64 -----------
// grid = (12, 12, 32), block = 256, dynamic smem 60672 B
__global__ void k3_kernel(const float* __restrict__ x,
                          const float* __restrict__ po_b,
                          float* __restrict__ out)
{
    extern __shared__ float sm[];
    float* xs   = sm;            // 6400  [10*10 pix][64]
    float* yT   = sm + 6400;     // 4096  [c][64 pix]
    float* kk_s = sm + 10496;    // 576   [tap][c]
    float* pw_s = sm + 11072;    // 4096  [c][o]

    const int t = threadIdx.x;
    const int b = blockIdx.z;
    const int r0 = blockIdx.y * 8, c0 = blockIdx.x * 8;

    // loads: x tile with halo (zero padded), kk, transposed po_w
    for (int i = t; i < 1600; i += 256) {
        const int pix = i >> 4, q = i & 15;
        const int py = pix / 10, px = pix - py * 10;
        const int gh = r0 - 1 + py, gw = c0 - 1 + px;
        float4 v = make_float4(0.f, 0.f, 0.f, 0.f);
        if ((unsigned)gh < 96u && (unsigned)gw < 96u)
            v = ldg4(&x[((size_t)b * 9216 + gh * 96 + gw) * 64 + q * 4]);
        *(float4*)&xs[pix * 64 + q * 4] = v;
    }
    if (t < 144) *(float4*)&kk_s[t * 4] = *(const float4*)&g_kk[b * 576 + t * 4];
    for (int i = t; i < 1024; i += 256) *(float4*)&pw_s[i * 4] = ldg4(&g_pwt[i * 4]);
    __syncthreads();

    // phase 1: depthwise 3x3 -> yT (transposed for GEMM-friendly phase 2)
    {
        const int p = t >> 2, sub = t & 3;
        const int row = p >> 3, col = p & 7;
        #pragma unroll
        for (int u = 0; u < 4; u++) {
            const int cb = sub * 16 + u * 4;
            float4 acc = make_float4(0.f, 0.f, 0.f, 0.f);
            #pragma unroll
            for (int dy = 0; dy < 3; dy++) {
                #pragma unroll
                for (int dx = 0; dx < 3; dx++) {
                    float4 kv = *(const float4*)&kk_s[(dy * 3 + dx) * 64 + cb];
                    float4 xv = *(const float4*)&xs[((row + dy) * 10 + col + dx) * 64 + cb];
                    acc.x = fmaf(kv.x, xv.x, acc.x);
                    acc.y = fmaf(kv.y, xv.y, acc.y);
                    acc.z = fmaf(kv.z, xv.z, acc.z);
                    acc.w = fmaf(kv.w, xv.w, acc.w);
                }
            }
            yT[(cb + 0) * 64 + p] = acc.x;
            yT[(cb + 1) * 64 + p] = acc.y;
            yT[(cb + 2) * 64 + p] = acc.z;
            yT[(cb + 3) * 64 + p] = acc.w;
        }
    }
    __syncthreads();

    // phase 2: out[p][o] = po_b[o] + sum_c yT[c][p] * pw_s[c][o]  (f32x2 packed)
    {
        const int po = t & 15, pg = t >> 4;
        const float4 bb = ldg4(&po_b[po * 4]);
        ull acc0[4], acc1[4];
        #pragma unroll
        for (int i = 0; i < 4; i++) { acc0[i] = pack2(bb.x, bb.y); acc1[i] = pack2(bb.z, bb.w); }

        #pragma unroll 4
        for (int c = 0; c < 64; c++) {
            const float4 w4 = *(const float4*)&pw_s[c * 64 + po * 4];
            const float4 y4 = *(const float4*)&yT[c * 64 + pg * 4];
            const ull w01 = pack2(w4.x, w4.y), w23 = pack2(w4.z, w4.w);
            ull yy;
            yy = pack2(y4.x, y4.x); fma2(acc0[0], w01, yy); fma2(acc1[0], w23, yy);
            yy = pack2(y4.y, y4.y); fma2(acc0[1], w01, yy); fma2(acc1[1], w23, yy);
            yy = pack2(y4.z, y4.z); fma2(acc0[2], w01, yy); fma2(acc1[2], w23, yy);
            yy = pack2(y4.w, y4.w); fma2(acc0[3], w01, yy); fma2(acc1[3], w23, yy);
        }

        #pragma unroll
        for (int i = 0; i < 4; i++) {
            const int p = pg * 4 + i;
            const int h = r0 + (p >> 3), wc = c0 + (p & 7);
            const float2 a = unpack2(acc0[i]);
            const float2 bq = unpack2(acc1[i]);
            *(float4*)&out[((size_t)b * 9216 + h * 96 + wc) * 64 + po * 4] =
                make_float4(a.x, a.y, bq.x, bq.y);
        }
    }
}

// ---------------- launch -----------------------------------------------------
extern "C" void kernel_launch(void* const* d_in, const int* in_sizes, int n_in,
                              void* d_out, int out_size) {
    const float* x        = (const float*)d_in[0];
    const float* se_w1    = (const float*)d_in[1];
    const float* se_b1    = (const float*)d_in[2];
    const float* se_w2    = (const float*)d_in[3];
    const float* se_b2    = (const float*)d_in[4];
    const float* dc_w     = (const float*)d_in[5];
    const float* dc_b     = (const float*)d_in[6];
    const float* l1_w     = (const float*)d_in[7];
    const float* l1_b     = (const float*)d_in[8];
    const float* l2_w     = (const float*)d_in[9];
    const float* l2_b     = (const float*)d_in[10];
    const float* gkf_w    = (const float*)d_in[11];
    const float* gkf_b    = (const float*)d_in[12];
    const float* fu_proj_w = (const float*)d_in[13];
    const float* fu_proj_b = (const float*)d_in[14];
    const float* fu_fc1_w = (const float*)d_in[15];
    const float* fu_fc1_b = (const float*)d_in[16];
    const float* fu_fc2_w = (const float*)d_in[17];
    const float* fu_fc2_b = (const float*)d_in[18];
    const float* fu_po_w  = (const float*)d_in[19];
    const float* fu_po_b  = (const float*)d_in[20];
    const float* po_w     = (const float*)d_in[21];
    const float* po_b     = (const float*)d_in[22];
    float* out = (float*)d_out;

    cudaFuncSetAttribute(k2_kernel, cudaFuncAttributeMaxDynamicSharedMemorySize, 56000);
    cudaFuncSetAttribute(k3_kernel, cudaFuncAttributeMaxDynamicSharedMemorySize, 61440);

    transpose_pw<<<1, 256>>>(po_w);
    pool_kernel<<<128, 768>>>(x);
    k2_kernel<<<32, 256, 54352>>>(se_w1, se_b1, se_w2, se_b2, dc_w, dc_b,
                                  l1_w, l1_b, l2_w, l2_b, gkf_w, gkf_b,
                                  fu_proj_w, fu_proj_b, fu_fc1_w, fu_fc1_b,
                                  fu_fc2_w, fu_fc2_b, fu_po_w, fu_po_b);
    dim3 grid(12, 12, 32);
    k3_kernel<<<grid, 256, 60672>>>(x, po_b, out);
}

// round 2
// speedup vs baseline: 1.6226x; 1.6226x over previous
#include <cuda_runtime.h>
#include <cuda_bf16.h>
#include <math.h>

typedef unsigned long long ull;

// ---------------- scratch (device globals; no allocation allowed) ----------
__device__ float g_kern[32 * 4 * 9 * 64];   // [b][w][pos][c] pooled kernels
__device__ float g_kk[32 * 9 * 64];         // [b][pos][c] effective dw kernel

// ---------------- helpers ---------------------------------------------------
__device__ __forceinline__ float gelu_exact(float x) {
    return 0.5f * x * (1.0f + erff(x * 0.70710678118654752440f));
}
__device__ __forceinline__ float sigm(float x) { return 1.0f / (1.0f + expf(-x)); }

__device__ __forceinline__ ull pack2(float lo, float hi) {
    ull r; asm("mov.b64 %0, {%1, %2};" : "=l"(r) : "f"(lo), "f"(hi)); return r;
}
__device__ __forceinline__ void fma2(ull& d, ull a, ull b) {
    asm("fma.rn.f32x2 %0, %1, %2, %0;" : "+l"(d) : "l"(a), "l"(b));
}
__device__ __forceinline__ float2 unpack2(ull v) {
    float2 r; asm("mov.b64 {%0, %1}, %2;" : "=f"(r.x), "=f"(r.y) : "l"(v)); return r;
}
__device__ __forceinline__ float4 ldg4(const float* p) {
    return __ldg((const float4*)p);
}

// ---------------- kernel 1: adaptive avg pool 48x48 -> 3x3 ------------------
// grid = 128 (b*4 + w), block = 768 (48 rows x 16 channel-quads)
__global__ void pool_kernel(const float* __restrict__ x) {
    __shared__ float4 part[48 * 3 * 16];   // [r][j][q]
    const int t = threadIdx.x;
    const int bw = blockIdx.x;
    const int b = bw >> 2, w = bw & 3;
    const int r = t >> 4, q = t & 15;
    const int wh0 = (w >> 1) * 48, ww0 = (w & 1) * 48;

    const float* xp = x + ((size_t)b * 9216 + (size_t)(wh0 + r) * 96 + ww0) * 64 + q * 4;

    #pragma unroll
    for (int j = 0; j < 3; j++) {
        float4 acc = make_float4(0.f, 0.f, 0.f, 0.f);
        #pragma unroll 4
        for (int cc = 0; cc < 16; cc++) {
            float4 v = ldg4(xp + (size_t)(j * 16 + cc) * 64);
            acc.x += v.x; acc.y += v.y; acc.z += v.z; acc.w += v.w;
        }
        part[(r * 3 + j) * 16 + q] = acc;
    }
    __syncthreads();

    if (t < 144) {
        const int q2 = t & 15, pos = t >> 4;
        const int i = pos / 3, j = pos - i * 3;
        float4 s = make_float4(0.f, 0.f, 0.f, 0.f);
        #pragma unroll
        for (int rr = 0; rr < 16; rr++) {
            float4 v = part[((i * 16 + rr) * 3 + j) * 16 + q2];
            s.x += v.x; s.y += v.y; s.z += v.z; s.w += v.w;
        }
        const float sc = 1.0f / 256.0f;
        s.x *= sc; s.y *= sc; s.z *= sc; s.w *= sc;
        *(float4*)&g_kern[((size_t)(b * 4 + w) * 9 + pos) * 64 + q2 * 4] = s;
    }
}

// ---------------- kernel 2: per-batch "brain" -> effective kernel kk --------
// grid = 32 (batch), block = 256, dynamic smem 54352 B
__global__ void k2_kernel(
    const float* __restrict__ se_w1, const float* __restrict__ se_b1,
    const float* __restrict__ se_w2, const float* __restrict__ se_b2,
    const float* __restrict__ dc_w,  const float* __restrict__ dc_b,
    const float* __restrict__ l1_w,  const float* __restrict__ l1_b,
    const float* __restrict__ l2_w,  const float* __restrict__ l2_b,
    const float* __restrict__ gkf_w, const float* __restrict__ gkf_b,
    const float* __restrict__ fu_proj_w, const float* __restrict__ fu_proj_b,
    const float* __restrict__ fu_fc1_w,  const float* __restrict__ fu_fc1_b,
    const float* __restrict__ fu_fc2_w,  const float* __restrict__ fu_fc2_b,
    const float* __restrict__ fu_po_w,   const float* __restrict__ fu_po_b)
{
    extern __shared__ float sm[];
    float* s_kern = sm;              // 2304  [w][pos][c]
    float* s_h1   = sm + 2304;       // 2304
    float* s_se   = sm + 4608;       // 2304  kern_se
    float* s_w    = sm + 6912;       // 4160  (64 rows, stride 65)
    float* s_gkf  = sm + 11072;      // 576   [pos][c]
    float* s_xsum = sm + 11648;      // 576   [pos][c]
    float* s_wm   = sm + 12224;      // 256   winmean [w][c]
    float* s_v0   = sm + 12480;      // 256
    float* s_red  = sm + 12736;      // 256
    float* s_v    = sm + 12992;      // 64
    float* s_log  = sm + 13056;      // 256
    float* s_av   = sm + 13312;      // 256
    float* s_l1   = sm + 13568;      // 16
    float* s_ww   = sm + 13584;      // 4

    const int t = threadIdx.x;
    const int b = blockIdx.x;

    // P0: load pooled kernels + se_w1 (padded)
    for (int i = t; i < 2304; i += 256) s_kern[i] = g_kern[b * 2304 + i];
    for (int i = t; i < 4096; i += 256) s_w[(i >> 6) * 65 + (i & 63)] = __ldg(&se_w1[i]);
    __syncthreads();

    // P1: SE layer 1 (gelu)
    #pragma unroll 1
    for (int k = 0; k < 9; k++) {
        const int out = t + 256 * k;
        const int c = out & 63, wp = out >> 6;
        float acc = __ldg(&se_b1[c]);
        const float* wr = &s_w[c * 65];
        const float* kr = &s_kern[wp * 64];
        #pragma unroll 8
        for (int ci = 0; ci < 64; ci++) acc = fmaf(wr[ci], kr[ci], acc);
        s_h1[wp * 64 + c] = gelu_exact(acc);
    }
    __syncthreads();
    for (int i = t; i < 4096; i += 256) s_w[(i >> 6) * 65 + (i & 63)] = __ldg(&se_w2[i]);
    __syncthreads();

    // P3: SE layer 2 (sigmoid) + window means
    #pragma unroll 1
    for (int k = 0; k < 9; k++) {
        const int out = t + 256 * k;
        const int c = out & 63, wp = out >> 6;
        float acc = __ldg(&se_b2[c]);
        const float* wr = &s_w[c * 65];
        const float* hr = &s_h1[wp * 64];
        #pragma unroll 8
        for (int ci = 0; ci < 64; ci++) acc = fmaf(wr[ci], hr[ci], acc);
        s_se[wp * 64 + c] = sigm(acc);
    }
    {
        const int w_ = t >> 6, c = t & 63;
        float s = 0.f;
        #pragma unroll
        for (int pos = 0; pos < 9; pos++) s += s_kern[w_ * 576 + pos * 64 + c];
        s_wm[t] = s * (1.0f / 9.0f);
    }
    __syncthreads();

    // P4: fusion proj + gelu + GAP -> v0   (thread = (g,o))
    {
        const int g = t >> 2, o = t & 3;
        const int wwin = g >> 4;
        float wreg[4];
        #pragma unroll
        for (int i = 0; i < 4; i++) wreg[i] = __ldg(&fu_proj_w[g * 16 + o * 4 + i]);
        const float bb = __ldg(&fu_proj_b[g * 4 + o]);
        float vs = 0.f;
        #pragma unroll
        for (int pos = 0; pos < 9; pos++) {
            float s = bb;
            #pragma unroll
            for (int i = 0; i < 4; i++) {
                const int c = ((g & 15) << 2) + i;
                s = fmaf(wreg[i], s_se[wwin * 576 + pos * 64 + c], s);
            }
            vs += gelu_exact(s);
        }
        s_v0[t] = vs * (1.0f / 9.0f);
    }
    __syncthreads();

    // P5: window reweight chain (warp 0)
    if (t < 32) {
        if (t < 4) {
            float a = __ldg(&dc_b[t]);
            for (int c = 0; c < 64; c++) a = fmaf(__ldg(&dc_w[t * 64 + c]), s_wm[t * 64 + c], a);
            s_ww[t] = a;
        }
        __syncwarp();
        if (t < 16) {
            float a = __ldg(&l1_b[t]);
            #pragma unroll
            for (int w = 0; w < 4; w++) a = fmaf(__ldg(&l1_w[t * 4 + w]), s_ww[w], a);
            s_l1[t] = gelu_exact(a);
        }
        __syncwarp();
        if (t < 4) {
            float a = __ldg(&l2_b[t]);
            #pragma unroll
            for (int j = 0; j < 16; j++) a = fmaf(__ldg(&l2_w[t * 16 + j]), s_l1[j], a);
            s_ww[t] = sigm(a);
        }
    }
    __syncthreads();

    // P6: fc1 (256 -> 64) with 4-way k split
    {
        const int c = t & 63, part = t >> 6;
        float acc = 0.f;
        const float* wp = &fu_fc1_w[c * 256 + part * 64];
        const float* vp = &s_v0[part * 64];
        #pragma unroll 4
        for (int kk = 0; kk < 16; kk++) {
            float4 a = ldg4(wp + kk * 4);
            float4 v4 = *(const float4*)(vp + kk * 4);
            acc += a.x * v4.x + a.y * v4.y + a.z * v4.z + a.w * v4.w;
        }
        s_red[t] = acc;
    }
    __syncthreads();
    if (t < 64)
        s_v[t] = gelu_exact(__ldg(&fu_fc1_b[t]) + s_red[t] + s_red[t + 64] + s_red[t + 128] + s_red[t + 192]);
    __syncthreads();

    // P7: fc2 logits (64 -> 256)
    {
        float acc = __ldg(&fu_fc2_b[t]);
        const float* wp = &fu_fc2_w[t * 64];
        #pragma unroll 4
        for (int kk = 0; kk < 16; kk++) {
            float4 a = ldg4(wp + kk * 4);
            float4 v4 = *(const float4*)&s_v[kk * 4];
            acc += a.x * v4.x + a.y * v4.y + a.z * v4.z + a.w * v4.w;
        }
        s_log[t] = acc;
    }
    __syncthreads();

    // P8: softmax over windows (per c), then gkf
    if (t < 64) {
        float m = s_log[t];
        #pragma unroll
        for (int w = 1; w < 4; w++) m = fmaxf(m, s_log[w * 64 + t]);
        float e[4]; float den = 0.f;
        #pragma unroll
        for (int w = 0; w < 4; w++) { e[w] = expf(s_log[w * 64 + t] - m); den += e[w]; }
        const float inv = 1.0f / den;
        #pragma unroll
        for (int w = 0; w < 4; w++) s_av[w * 64 + t] = e[w] * inv;
    }
    __syncthreads();

    #pragma unroll 1
    for (int k = 0; k < 3; k++) {
        const int out = t + 256 * k;
        if (out < 576) {
            const int c = out & 63, pos = out >> 6;
            float a = __ldg(&gkf_b[c]);
            float xsum = 0.f;
            #pragma unroll
            for (int w = 0; w < 4; w++) {
                const float se = s_se[w * 576 + pos * 64 + c];
                a = fmaf(__ldg(&gkf_w[c * 4 + w]) * s_ww[w], se, a);
                xsum = fmaf(s_av[w * 64 + c], se, xsum);
            }
            s_gkf[pos * 64 + c] = a;
            s_xsum[pos * 64 + c] = xsum;
        }
    }
    for (int i = t; i < 4096; i += 256) s_w[(i >> 6) * 65 + (i & 63)] = __ldg(&fu_po_w[i]);
    __syncthreads();

    // P10: gks_extra = fu_po(x_sum); kk = 2*gkf + gks_extra
    #pragma unroll 1
    for (int k = 0; k < 3; k++) {
        const int out = t + 256 * k;
        if (out < 576) {
            const int c = out & 63, pos = out >> 6;
            float a = __ldg(&fu_po_b[c]);
            const float* wr = &s_w[c * 65];
            const float* xr = &s_xsum[pos * 64];
            #pragma unroll 8
            for (int ci = 0; ci < 64; ci++) a = fmaf(wr[ci], xr[ci], a);
            g_kk[b * 576 + pos * 64 + c] = 2.0f * s_gkf[pos * 64 + c] + a;
        }
    }
}

// ---------------- kernel 3: fused depthwise 3x3 + pointwise 64x64 -----------
// 16x16 pixel tile per block. grid = (6, 6, 32), block = 256.
// smem floats: xs[18][364] chunked (16 ch, col stride 20), yT[64][260],
//              pw[64][68] (transposed po_w), kk[9][64]
#define XS_OFF 0
#define XS_RS  364
#define YT_OFF 6552
#define YT_RS  260
#define PW_OFF 23192
#define PW_RS  68
#define KK_OFF 27544
#define K3_SMEM_FLOATS 28120

__global__ void __launch_bounds__(256, 2) k3_kernel(
    const float* __restrict__ x,
    const float* __restrict__ po_w,
    const float* __restrict__ po_b,
    float* __restrict__ out)
{
    extern __shared__ float sm[];
    float* xs   = sm + XS_OFF;
    float* yT   = sm + YT_OFF;
    float* pw_s = sm + PW_OFF;
    float* kk_s = sm + KK_OFF;

    const int t = threadIdx.x;
    const int b = blockIdx.z;
    const int r0 = blockIdx.y * 16, c0 = blockIdx.x * 16;
    const size_t xbase = (size_t)b * 9216;

    // one-time loads: kk, transposed po_w
    if (t < 144) *(float4*)&kk_s[t * 4] = *(const float4*)&g_kk[b * 576 + t * 4];
    #pragma unroll
    for (int i = t; i < 4096; i += 256) {
        const int o = i >> 6, c = i & 63;
        pw_s[c * PW_RS + o] = __ldg(&po_w[i]);
    }

    // ---- phase 1: depthwise 3x3, 4 channel-chunks of 16 ----
    const int row  = t >> 4;          // 0..15
    const int colg = (t >> 2) & 3;    // 0..3 (4-pixel column group)
    const int q    = t & 3;           // channel quad within chunk

    #pragma unroll 1
    for (int cc = 0; cc < 4; cc++) {
        __syncthreads();   // protect xs reuse (and first iter: kk/pw ordering)
        // load x chunk (18x18 halo, 16 channels), zero-pad OOB
        #pragma unroll 1
        for (int i = t; i < 1296; i += 256) {
            const int pix = i >> 2, qq = i & 3;
            const int py = pix / 18, px = pix - py * 18;
            const int gh = r0 - 1 + py, gw = c0 - 1 + px;
            float4 v = make_float4(0.f, 0.f, 0.f, 0.f);
            if ((unsigned)gh < 96u && (unsigned)gw < 96u)
                v = ldg4(&x[(xbase + gh * 96 + gw) * 64 + cc * 16 + qq * 4]);
            *(float4*)&xs[py * XS_RS + px * 20 + qq * 4] = v;
        }
        __syncthreads();

        // compute: 4 output cols x 4 channels per thread, f32x2
        ull acc2[4][2];
        #pragma unroll
        for (int j = 0; j < 4; j++) { acc2[j][0] = 0ull; acc2[j][1] = 0ull; }

        const ulonglong2* xs2 = (const ulonglong2*)xs;
        const ulonglong2* kk2 = (const ulonglong2*)kk_s;

        #pragma unroll
        for (int dy = 0; dy < 3; dy++) {
            ulonglong2 xv[6];
            #pragma unroll
            for (int dx = 0; dx < 6; dx++)
                xv[dx] = xs2[((row + dy) * XS_RS + (colg * 4 + dx) * 20) / 4 + q];
            #pragma unroll
            for (int dx = 0; dx < 3; dx++) {
                const ulonglong2 kv = kk2[(dy * 3 + dx) * 16 + cc * 4 + q];
                #pragma unroll
                for (int j = 0; j < 4; j++) {
                    fma2(acc2[j][0], kv.x, xv[j + dx].x);
                    fma2(acc2[j][1], kv.y, xv[j + dx].y);
                }
            }
        }

        // transpose to yT[c][pix]
        float v[4][4];
        #pragma unroll
        for (int j = 0; j < 4; j++) {
            const float2 p0 = unpack2(acc2[j][0]);
            const float2 p1 = unpack2(acc2[j][1]);
            v[j][0] = p0.x; v[j][1] = p0.y; v[j][2] = p1.x; v[j][3] = p1.y;
        }
        #pragma unroll
        for (int i = 0; i < 4; i++) {
            *(float4*)&yT[(cc * 16 + q * 4 + i) * YT_RS + row * 16 + colg * 4] =
                make_float4(v[0][i], v[1][i], v[2][i], v[3][i]);
        }
    }
    __syncthreads();

    // ---- phase 2: pointwise 64x64 GEMM over 256 pixels ----
    {
        const int w = t >> 5;   // warp -> outs [8w, 8w+8)
        const int l = t & 31;   // lane -> pixels {4l..4l+3} and {128+4l..+3}

        // init accumulators with bias
        const float4 b0 = ldg4(&po_b[8 * w]);
        const float4 b1 = ldg4(&po_b[8 * w + 4]);
        ull acc[2][4][4];
        #pragma unroll
        for (int k = 0; k < 2; k++)
            #pragma unroll
            for (int i = 0; i < 4; i++) {
                acc[k][i][0] = pack2(b0.x, b0.y);
                acc[k][i][1] = pack2(b0.z, b0.w);
                acc[k][i][2] = pack2(b1.x, b1.y);
                acc[k][i][3] = pack2(b1.z, b1.w);
            }

        const float4* yT4 = (const float4*)yT;
        const float4* pw4 = (const float4*)pw_s;

        #pragma unroll 4
        for (int c = 0; c < 64; c++) {
            const float4 ya = yT4[c * (YT_RS / 4) + l];
            const float4 yb = yT4[c * (YT_RS / 4) + 32 + l];
            const float4 w0 = pw4[c * (PW_RS / 4) + 2 * w];
            const float4 w1 = pw4[c * (PW_RS / 4) + 2 * w + 1];
            ull W[4];
            W[0] = pack2(w0.x, w0.y); W[1] = pack2(w0.z, w0.w);
            W[2] = pack2(w1.x, w1.y); W[3] = pack2(w1.z, w1.w);

            ull yy;
            yy = pack2(ya.x, ya.x);
            fma2(acc[0][0][0], W[0], yy); fma2(acc[0][0][1], W[1], yy);
            fma2(acc[0][0][2], W[2], yy); fma2(acc[0][0][3], W[3], yy);
            yy = pack2(ya.y, ya.y);
            fma2(acc[0][1][0], W[0], yy); fma2(acc[0][1][1], W[1], yy);
            fma2(acc[0][1][2], W[2], yy); fma2(acc[0][1][3], W[3], yy);
            yy = pack2(ya.z, ya.z);
            fma2(acc[0][2][0], W[0], yy); fma2(acc[0][2][1], W[1], yy);
            fma2(acc[0][2][2], W[2], yy); fma2(acc[0][2][3], W[3], yy);
            yy = pack2(ya.w, ya.w);
            fma2(acc[0][3][0], W[0], yy); fma2(acc[0][3][1], W[1], yy);
            fma2(acc[0][3][2], W[2], yy); fma2(acc[0][3][3], W[3], yy);

            yy = pack2(yb.x, yb.x);
            fma2(acc[1][0][0], W[0], yy); fma2(acc[1][0][1], W[1], yy);
            fma2(acc[1][0][2], W[2], yy); fma2(acc[1][0][3], W[3], yy);
            yy = pack2(yb.y, yb.y);
            fma2(acc[1][1][0], W[0], yy); fma2(acc[1][1][1], W[1], yy);
            fma2(acc[1][1][2], W[2], yy); fma2(acc[1][1][3], W[3], yy);
            yy = pack2(yb.z, yb.z);
            fma2(acc[1][2][0], W[0], yy); fma2(acc[1][2][1], W[1], yy);
            fma2(acc[1][2][2], W[2], yy); fma2(acc[1][2][3], W[3], yy);
            yy = pack2(yb.w, yb.w);
            fma2(acc[1][3][0], W[0], yy); fma2(acc[1][3][1], W[1], yy);
            fma2(acc[1][3][2], W[2], yy); fma2(acc[1][3][3], W[3], yy);
        }

        // store: each (k,i) pixel gets 8 consecutive outs (one 32B sector)
        #pragma unroll
        for (int k = 0; k < 2; k++) {
            #pragma unroll
            for (int i = 0; i < 4; i++) {
                const int pix = k * 128 + 4 * l + i;
                const int h = r0 + (pix >> 4), wc = c0 + (pix & 15);
                float* op = &out[(xbase + h * 96 + wc) * 64 + 8 * w];
                const float2 a0 = unpack2(acc[k][i][0]);
                const float2 a1 = unpack2(acc[k][i][1]);
                const float2 a2 = unpack2(acc[k][i][2]);
                const float2 a3 = unpack2(acc[k][i][3]);
                *(float4*)op       = make_float4(a0.x, a0.y, a1.x, a1.y);
                *(float4*)(op + 4) = make_float4(a2.x, a2.y, a3.x, a3.y);
            }
        }
    }
}

// ---------------- launch -----------------------------------------------------
extern "C" void kernel_launch(void* const* d_in, const int* in_sizes, int n_in,
                              void* d_out, int out_size) {
    const float* x        = (const float*)d_in[0];
    const float* se_w1    = (const float*)d_in[1];
    const float* se_b1    = (const float*)d_in[2];
    const float* se_w2    = (const float*)d_in[3];
    const float* se_b2    = (const float*)d_in[4];
    const float* dc_w     = (const float*)d_in[5];
    const float* dc_b     = (const float*)d_in[6];
    const float* l1_w     = (const float*)d_in[7];
    const float* l1_b     = (const float*)d_in[8];
    const float* l2_w     = (const float*)d_in[9];
    const float* l2_b     = (const float*)d_in[10];
    const float* gkf_w    = (const float*)d_in[11];
    const float* gkf_b    = (const float*)d_in[12];
    const float* fu_proj_w = (const float*)d_in[13];
    const float* fu_proj_b = (const float*)d_in[14];
    const float* fu_fc1_w = (const float*)d_in[15];
    const float* fu_fc1_b = (const float*)d_in[16];
    const float* fu_fc2_w = (const float*)d_in[17];
    const float* fu_fc2_b = (const float*)d_in[18];
    const float* fu_po_w  = (const float*)d_in[19];
    const float* fu_po_b  = (const float*)d_in[20];
    const float* po_w     = (const float*)d_in[21];
    const float* po_b     = (const float*)d_in[22];
    float* out = (float*)d_out;

    cudaFuncSetAttribute(k2_kernel, cudaFuncAttributeMaxDynamicSharedMemorySize, 56000);
    cudaFuncSetAttribute(k3_kernel, cudaFuncAttributeMaxDynamicSharedMemorySize,
                         K3_SMEM_FLOATS * 4);

    pool_kernel<<<128, 768>>>(x);
    k2_kernel<<<32, 256, 54352>>>(se_w1, se_b1, se_w2, se_b2, dc_w, dc_b,
                                  l1_w, l1_b, l2_w, l2_b, gkf_w, gkf_b,
                                  fu_proj_w, fu_proj_b, fu_fc1_w, fu_fc1_b,
                                  fu_fc2_w, fu_fc2_b, fu_po_w, fu_po_b);
    dim3 grid(6, 6, 32);
    k3_kernel<<<grid, 256, K3_SMEM_FLOATS * 4>>>(x, po_w, po_b, out);
}

// round 3
// speedup vs baseline: 1.6464x; 1.0147x over previous
#include <cuda_runtime.h>
#include <cuda_bf16.h>
#include <math.h>

typedef unsigned long long ull;

// ---------------- scratch (device globals; no allocation allowed) ----------
__device__ float g_kern[32 * 4 * 9 * 64];   // [b][w][pos][c] pooled kernels
__device__ float g_kk[32 * 9 * 64];         // [b][pos][c] effective dw kernel

// ---------------- helpers ---------------------------------------------------
__device__ __forceinline__ float gelu_exact(float x) {
    return 0.5f * x * (1.0f + erff(x * 0.70710678118654752440f));
}
__device__ __forceinline__ float sigm(float x) { return 1.0f / (1.0f + expf(-x)); }

__device__ __forceinline__ ull pack2(float lo, float hi) {
    ull r; asm("mov.b64 %0, {%1, %2};" : "=l"(r) : "f"(lo), "f"(hi)); return r;
}
__device__ __forceinline__ void fma2(ull& d, ull a, ull b) {
    asm("fma.rn.f32x2 %0, %1, %2, %0;" : "+l"(d) : "l"(a), "l"(b));
}
__device__ __forceinline__ float2 unpack2(ull v) {
    float2 r; asm("mov.b64 {%0, %1}, %2;" : "=f"(r.x), "=f"(r.y) : "l"(v)); return r;
}
__device__ __forceinline__ float4 ldg4(const float* p) {
    return __ldg((const float4*)p);
}

// ---------------- kernel 1: adaptive avg pool 48x48 -> 3x3 ------------------
// grid = (9, 128): x = pos (i*3+j), y = b*4+w. block = 256 (16 rows x 16 quads)
__global__ void pool_kernel(const float* __restrict__ x) {
    __shared__ float4 part[16][16];
    const int t = threadIdx.x;
    const int pos = blockIdx.x;
    const int bw = blockIdx.y;
    const int b = bw >> 2, w = bw & 3;
    const int i = pos / 3, j = pos - i * 3;
    const int r = t >> 4, q = t & 15;
    const int gh = (w >> 1) * 48 + i * 16 + r;
    const int gw0 = (w & 1) * 48 + j * 16;

    const float* xp = x + ((size_t)b * 9216 + (size_t)gh * 96 + gw0) * 64 + q * 4;

    float4 a0 = make_float4(0.f, 0.f, 0.f, 0.f);
    float4 a1 = make_float4(0.f, 0.f, 0.f, 0.f);
    #pragma unroll
    for (int cc = 0; cc < 16; cc += 2) {
        float4 v0 = ldg4(xp + (size_t)cc * 64);
        float4 v1 = ldg4(xp + (size_t)(cc + 1) * 64);
        a0.x += v0.x; a0.y += v0.y; a0.z += v0.z; a0.w += v0.w;
        a1.x += v1.x; a1.y += v1.y; a1.z += v1.z; a1.w += v1.w;
    }
    a0.x += a1.x; a0.y += a1.y; a0.z += a1.z; a0.w += a1.w;
    part[r][q] = a0;
    __syncthreads();

    if (t < 64) {
        const int qq = t & 15, seg = t >> 4;
        float4 s = make_float4(0.f, 0.f, 0.f, 0.f);
        #pragma unroll
        for (int rr = 0; rr < 4; rr++) {
            float4 v = part[seg * 4 + rr][qq];
            s.x += v.x; s.y += v.y; s.z += v.z; s.w += v.w;
        }
        part[seg][qq] = s;   // seg rows 0..3 only re-read by their own writers
    }
    __syncthreads();
    if (t < 16) {
        float4 s = make_float4(0.f, 0.f, 0.f, 0.f);
        #pragma unroll
        for (int seg = 0; seg < 4; seg++) {
            float4 v = part[seg][t];
            s.x += v.x; s.y += v.y; s.z += v.z; s.w += v.w;
        }
        const float sc = 1.0f / 256.0f;
        s.x *= sc; s.y *= sc; s.z *= sc; s.w *= sc;
        *(float4*)&g_kern[((size_t)bw * 9 + pos) * 64 + t * 4] = s;
    }
}

// ---------------- kernel 2: per-batch "brain" -> effective kernel kk --------
// grid = 32 (batch), block = 256, dynamic smem 54352 B
__global__ void k2_kernel(
    const float* __restrict__ se_w1, const float* __restrict__ se_b1,
    const float* __restrict__ se_w2, const float* __restrict__ se_b2,
    const float* __restrict__ dc_w,  const float* __restrict__ dc_b,
    const float* __restrict__ l1_w,  const float* __restrict__ l1_b,
    const float* __restrict__ l2_w,  const float* __restrict__ l2_b,
    const float* __restrict__ gkf_w, const float* __restrict__ gkf_b,
    const float* __restrict__ fu_proj_w, const float* __restrict__ fu_proj_b,
    const float* __restrict__ fu_fc1_w,  const float* __restrict__ fu_fc1_b,
    const float* __restrict__ fu_fc2_w,  const float* __restrict__ fu_fc2_b,
    const float* __restrict__ fu_po_w,   const float* __restrict__ fu_po_b)
{
    extern __shared__ float sm[];
    float* s_kern = sm;              // 2304  [w][pos][c]
    float* s_h1   = sm + 2304;       // 2304
    float* s_se   = sm + 4608;       // 2304  kern_se
    float* s_w    = sm + 6912;       // 4160  (64 rows, stride 65)
    float* s_gkf  = sm + 11072;      // 576   [pos][c]
    float* s_xsum = sm + 11648;      // 576   [pos][c]
    float* s_wm   = sm + 12224;      // 256   winmean [w][c]
    float* s_v0   = sm + 12480;      // 256
    float* s_red  = sm + 12736;      // 256
    float* s_v    = sm + 12992;      // 64
    float* s_log  = sm + 13056;      // 256
    float* s_av   = sm + 13312;      // 256
    float* s_l1   = sm + 13568;      // 16
    float* s_ww   = sm + 13584;      // 4

    const int t = threadIdx.x;
    const int b = blockIdx.x;

    // P0: load pooled kernels + se_w1 (padded)
    for (int i = t; i < 2304; i += 256) s_kern[i] = g_kern[b * 2304 + i];
    for (int i = t; i < 4096; i += 256) s_w[(i >> 6) * 65 + (i & 63)] = __ldg(&se_w1[i]);
    __syncthreads();

    // P1: SE layer 1 (gelu)
    #pragma unroll 1
    for (int k = 0; k < 9; k++) {
        const int out = t + 256 * k;
        const int c = out & 63, wp = out >> 6;
        const float* wr = &s_w[c * 65];
        const float* kr = &s_kern[wp * 64];
        float a0 = 0.f, a1 = 0.f, a2 = 0.f, a3 = 0.f;
        #pragma unroll
        for (int ci = 0; ci < 16; ci++) {
            a0 = fmaf(wr[4 * ci + 0], kr[4 * ci + 0], a0);
            a1 = fmaf(wr[4 * ci + 1], kr[4 * ci + 1], a1);
            a2 = fmaf(wr[4 * ci + 2], kr[4 * ci + 2], a2);
            a3 = fmaf(wr[4 * ci + 3], kr[4 * ci + 3], a3);
        }
        s_h1[wp * 64 + c] = gelu_exact(__ldg(&se_b1[c]) + (a0 + a1) + (a2 + a3));
    }
    __syncthreads();
    for (int i = t; i < 4096; i += 256) s_w[(i >> 6) * 65 + (i & 63)] = __ldg(&se_w2[i]);
    __syncthreads();

    // P3: SE layer 2 (sigmoid) + window means
    #pragma unroll 1
    for (int k = 0; k < 9; k++) {
        const int out = t + 256 * k;
        const int c = out & 63, wp = out >> 6;
        const float* wr = &s_w[c * 65];
        const float* hr = &s_h1[wp * 64];
        float a0 = 0.f, a1 = 0.f, a2 = 0.f, a3 = 0.f;
        #pragma unroll
        for (int ci = 0; ci < 16; ci++) {
            a0 = fmaf(wr[4 * ci + 0], hr[4 * ci + 0], a0);
            a1 = fmaf(wr[4 * ci + 1], hr[4 * ci + 1], a1);
            a2 = fmaf(wr[4 * ci + 2], hr[4 * ci + 2], a2);
            a3 = fmaf(wr[4 * ci + 3], hr[4 * ci + 3], a3);
        }
        s_se[wp * 64 + c] = sigm(__ldg(&se_b2[c]) + (a0 + a1) + (a2 + a3));
    }
    {
        const int w_ = t >> 6, c = t & 63;
        float s = 0.f;
        #pragma unroll
        for (int pos = 0; pos < 9; pos++) s += s_kern[w_ * 576 + pos * 64 + c];
        s_wm[t] = s * (1.0f / 9.0f);
    }
    __syncthreads();

    // P4: fusion proj + gelu + GAP -> v0   (thread = (g,o))
    {
        const int g = t >> 2, o = t & 3;
        const int wwin = g >> 4;
        float wreg[4];
        #pragma unroll
        for (int i = 0; i < 4; i++) wreg[i] = __ldg(&fu_proj_w[g * 16 + o * 4 + i]);
        const float bb = __ldg(&fu_proj_b[g * 4 + o]);
        float vs = 0.f;
        #pragma unroll
        for (int pos = 0; pos < 9; pos++) {
            float s = bb;
            #pragma unroll
            for (int i = 0; i < 4; i++) {
                const int c = ((g & 15) << 2) + i;
                s = fmaf(wreg[i], s_se[wwin * 576 + pos * 64 + c], s);
            }
            vs += gelu_exact(s);
        }
        s_v0[t] = vs * (1.0f / 9.0f);
    }
    __syncthreads();

    // P5: window reweight chain (warp 0)
    if (t < 32) {
        if (t < 4) {
            float a0 = 0.f, a1 = 0.f, a2 = 0.f, a3 = 0.f;
            #pragma unroll
            for (int c = 0; c < 16; c++) {
                a0 = fmaf(__ldg(&dc_w[t * 64 + 4 * c + 0]), s_wm[t * 64 + 4 * c + 0], a0);
                a1 = fmaf(__ldg(&dc_w[t * 64 + 4 * c + 1]), s_wm[t * 64 + 4 * c + 1], a1);
                a2 = fmaf(__ldg(&dc_w[t * 64 + 4 * c + 2]), s_wm[t * 64 + 4 * c + 2], a2);
                a3 = fmaf(__ldg(&dc_w[t * 64 + 4 * c + 3]), s_wm[t * 64 + 4 * c + 3], a3);
            }
            s_ww[t] = __ldg(&dc_b[t]) + (a0 + a1) + (a2 + a3);
        }
        __syncwarp();
        if (t < 16) {
            float a = __ldg(&l1_b[t]);
            #pragma unroll
            for (int w = 0; w < 4; w++) a = fmaf(__ldg(&l1_w[t * 4 + w]), s_ww[w], a);
            s_l1[t] = gelu_exact(a);
        }
        __syncwarp();
        if (t < 4) {
            float a = __ldg(&l2_b[t]);
            #pragma unroll
            for (int j = 0; j < 16; j++) a = fmaf(__ldg(&l2_w[t * 16 + j]), s_l1[j], a);
            s_ww[t] = sigm(a);
        }
    }
    __syncthreads();

    // P6: fc1 (256 -> 64) with 4-way k split
    {
        const int c = t & 63, part = t >> 6;
        float acc = 0.f;
        const float* wp = &fu_fc1_w[c * 256 + part * 64];
        const float* vp = &s_v0[part * 64];
        #pragma unroll 4
        for (int kk = 0; kk < 16; kk++) {
            float4 a = ldg4(wp + kk * 4);
            float4 v4 = *(const float4*)(vp + kk * 4);
            acc += a.x * v4.x + a.y * v4.y + a.z * v4.z + a.w * v4.w;
        }
        s_red[t] = acc;
    }
    __syncthreads();
    if (t < 64)
        s_v[t] = gelu_exact(__ldg(&fu_fc1_b[t]) + s_red[t] + s_red[t + 64] + s_red[t + 128] + s_red[t + 192]);
    __syncthreads();

    // P7: fc2 logits (64 -> 256)
    {
        float acc = __ldg(&fu_fc2_b[t]);
        const float* wp = &fu_fc2_w[t * 64];
        #pragma unroll 4
        for (int kk = 0; kk < 16; kk++) {
            float4 a = ldg4(wp + kk * 4);
            float4 v4 = *(const float4*)&s_v[kk * 4];
            acc += a.x * v4.x + a.y * v4.y + a.z * v4.z + a.w * v4.w;
        }
        s_log[t] = acc;
    }
    __syncthreads();

    // P8: softmax over windows (per c), then gkf
    if (t < 64) {
        float m = s_log[t];
        #pragma unroll
        for (int w = 1; w < 4; w++) m = fmaxf(m, s_log[w * 64 + t]);
        float e[4]; float den = 0.f;
        #pragma unroll
        for (int w = 0; w < 4; w++) { e[w] = expf(s_log[w * 64 + t] - m); den += e[w]; }
        const float inv = 1.0f / den;
        #pragma unroll
        for (int w = 0; w < 4; w++) s_av[w * 64 + t] = e[w] * inv;
    }
    __syncthreads();

    #pragma unroll 1
    for (int k = 0; k < 3; k++) {
        const int out = t + 256 * k;
        if (out < 576) {
            const int c = out & 63, pos = out >> 6;
            float a = __ldg(&gkf_b[c]);
            float xsum = 0.f;
            #pragma unroll
            for (int w = 0; w < 4; w++) {
                const float se = s_se[w * 576 + pos * 64 + c];
                a = fmaf(__ldg(&gkf_w[c * 4 + w]) * s_ww[w], se, a);
                xsum = fmaf(s_av[w * 64 + c], se, xsum);
            }
            s_gkf[pos * 64 + c] = a;
            s_xsum[pos * 64 + c] = xsum;
        }
    }
    for (int i = t; i < 4096; i += 256) s_w[(i >> 6) * 65 + (i & 63)] = __ldg(&fu_po_w[i]);
    __syncthreads();

    // P10: gks_extra = fu_po(x_sum); kk = 2*gkf + gks_extra
    #pragma unroll 1
    for (int k = 0; k < 3; k++) {
        const int out = t + 256 * k;
        if (out < 576) {
            const int c = out & 63, pos = out >> 6;
            const float* wr = &s_w[c * 65];
            const float* xr = &s_xsum[pos * 64];
            float a0 = 0.f, a1 = 0.f, a2 = 0.f, a3 = 0.f;
            #pragma unroll
            for (int ci = 0; ci < 16; ci++) {
                a0 = fmaf(wr[4 * ci + 0], xr[4 * ci + 0], a0);
                a1 = fmaf(wr[4 * ci + 1], xr[4 * ci + 1], a1);
                a2 = fmaf(wr[4 * ci + 2], xr[4 * ci + 2], a2);
                a3 = fmaf(wr[4 * ci + 3], xr[4 * ci + 3], a3);
            }
            g_kk[b * 576 + pos * 64 + c] =
                2.0f * s_gkf[pos * 64 + c] + __ldg(&fu_po_b[c]) + (a0 + a1) + (a2 + a3);
        }
    }
}

// ---------------- kernel 3: fused depthwise 3x3 + pointwise 64x64 -----------
// 16x16 pixel tile per block. grid = (6, 6, 32), block = 256.
#define XS_OFF 0
#define XS_RS  364
#define YT_OFF 6552
#define YT_RS  260
#define PW_OFF 23192
#define PW_RS  68
#define KK_OFF 27544
#define K3_SMEM_FLOATS 28120

__global__ void __launch_bounds__(256, 2) k3_kernel(
    const float* __restrict__ x,
    const float* __restrict__ po_w,
    const float* __restrict__ po_b,
    float* __restrict__ out)
{
    extern __shared__ float sm[];
    float* xs   = sm + XS_OFF;
    float* yT   = sm + YT_OFF;
    float* pw_s = sm + PW_OFF;
    float* kk_s = sm + KK_OFF;

    const int t = threadIdx.x;
    const int b = blockIdx.z;
    const int r0 = blockIdx.y * 16, c0 = blockIdx.x * 16;
    const size_t xbase = (size_t)b * 9216;

    // one-time loads: kk, transposed po_w
    if (t < 144) *(float4*)&kk_s[t * 4] = *(const float4*)&g_kk[b * 576 + t * 4];
    #pragma unroll
    for (int i = t; i < 4096; i += 256) {
        const int o = i >> 6, c = i & 63;
        pw_s[c * PW_RS + o] = __ldg(&po_w[i]);
    }

    // ---- phase 1: depthwise 3x3, 4 channel-chunks of 16 ----
    const int row  = t >> 4;          // 0..15
    const int colg = (t >> 2) & 3;    // 0..3 (4-pixel column group)
    const int q    = t & 3;           // channel quad within chunk

    #pragma unroll 1
    for (int cc = 0; cc < 4; cc++) {
        __syncthreads();   // protect xs reuse (and first iter: kk/pw ordering)
        #pragma unroll 1
        for (int i = t; i < 1296; i += 256) {
            const int pix = i >> 2, qq = i & 3;
            const int py = pix / 18, px = pix - py * 18;
            const int gh = r0 - 1 + py, gw = c0 - 1 + px;
            float4 v = make_float4(0.f, 0.f, 0.f, 0.f);
            if ((unsigned)gh < 96u && (unsigned)gw < 96u)
                v = ldg4(&x[(xbase + gh * 96 + gw) * 64 + cc * 16 + qq * 4]);
            *(float4*)&xs[py * XS_RS + px * 20 + qq * 4] = v;
        }
        __syncthreads();

        ull acc2[4][2];
        #pragma unroll
        for (int j = 0; j < 4; j++) { acc2[j][0] = 0ull; acc2[j][1] = 0ull; }

        const ulonglong2* xs2 = (const ulonglong2*)xs;
        const ulonglong2* kk2 = (const ulonglong2*)kk_s;

        #pragma unroll
        for (int dy = 0; dy < 3; dy++) {
            ulonglong2 xv[6];
            #pragma unroll
            for (int dx = 0; dx < 6; dx++)
                xv[dx] = xs2[((row + dy) * XS_RS + (colg * 4 + dx) * 20) / 4 + q];
            #pragma unroll
            for (int dx = 0; dx < 3; dx++) {
                const ulonglong2 kv = kk2[(dy * 3 + dx) * 16 + cc * 4 + q];
                #pragma unroll
                for (int j = 0; j < 4; j++) {
                    fma2(acc2[j][0], kv.x, xv[j + dx].x);
                    fma2(acc2[j][1], kv.y, xv[j + dx].y);
                }
            }
        }

        float v[4][4];
        #pragma unroll
        for (int j = 0; j < 4; j++) {
            const float2 p0 = unpack2(acc2[j][0]);
            const float2 p1 = unpack2(acc2[j][1]);
            v[j][0] = p0.x; v[j][1] = p0.y; v[j][2] = p1.x; v[j][3] = p1.y;
        }
        #pragma unroll
        for (int i = 0; i < 4; i++) {
            *(float4*)&yT[(cc * 16 + q * 4 + i) * YT_RS + row * 16 + colg * 4] =
                make_float4(v[0][i], v[1][i], v[2][i], v[3][i]);
        }
    }
    __syncthreads();

    // ---- phase 2: pointwise 64x64 GEMM, pixel-pair packed f32x2 ----
    {
        const int og = t >> 4;    // 0..15 -> outs og*4..+3
        const int pl = t & 15;    // pixel lane
        const float4 bias = ldg4(&po_b[og * 4]);
        const ull binit[4] = { pack2(bias.x, bias.x), pack2(bias.y, bias.y),
                               pack2(bias.z, bias.z), pack2(bias.w, bias.w) };

        #pragma unroll 1
        for (int k = 0; k < 2; k++) {
            const int pbase = 64 * k + pl * 4;
            ull acc[4][4];   // [out o][pair: A0 A1 B0 B1]
            #pragma unroll
            for (int o = 0; o < 4; o++) {
                acc[o][0] = binit[o]; acc[o][1] = binit[o];
                acc[o][2] = binit[o]; acc[o][3] = binit[o];
            }

            #pragma unroll 4
            for (int c = 0; c < 64; c++) {
                const ulonglong2 ya = *(const ulonglong2*)&yT[c * YT_RS + pbase];
                const ulonglong2 yb = *(const ulonglong2*)&yT[c * YT_RS + pbase + 128];
                const float4 wv = *(const float4*)&pw_s[c * PW_RS + og * 4];
                ull w;
                w = pack2(wv.x, wv.x);
                fma2(acc[0][0], w, ya.x); fma2(acc[0][1], w, ya.y);
                fma2(acc[0][2], w, yb.x); fma2(acc[0][3], w, yb.y);
                w = pack2(wv.y, wv.y);
                fma2(acc[1][0], w, ya.x); fma2(acc[1][1], w, ya.y);
                fma2(acc[1][2], w, yb.x); fma2(acc[1][3], w, yb.y);
                w = pack2(wv.z, wv.z);
                fma2(acc[2][0], w, ya.x); fma2(acc[2][1], w, ya.y);
                fma2(acc[2][2], w, yb.x); fma2(acc[2][3], w, yb.y);
                w = pack2(wv.w, wv.w);
                fma2(acc[3][0], w, ya.x); fma2(acc[3][1], w, ya.y);
                fma2(acc[3][2], w, yb.x); fma2(acc[3][3], w, yb.y);
            }

            // epilogue: unpack & store 8 pixels x 4 outs
            float va[4][4], vb[4][4];
            #pragma unroll
            for (int o = 0; o < 4; o++) {
                float2 u0 = unpack2(acc[o][0]); va[o][0] = u0.x; va[o][1] = u0.y;
                float2 u1 = unpack2(acc[o][1]); va[o][2] = u1.x; va[o][3] = u1.y;
                float2 u2 = unpack2(acc[o][2]); vb[o][0] = u2.x; vb[o][1] = u2.y;
                float2 u3 = unpack2(acc[o][3]); vb[o][2] = u3.x; vb[o][3] = u3.y;
            }
            #pragma unroll
            for (int e = 0; e < 4; e++) {
                int pix = pbase + e;
                int h = r0 + (pix >> 4), wc = c0 + (pix & 15);
                *(float4*)&out[(xbase + h * 96 + wc) * 64 + og * 4] =
                    make_float4(va[0][e], va[1][e], va[2][e], va[3][e]);
                pix = pbase + 128 + e;
                h = r0 + (pix >> 4); wc = c0 + (pix & 15);
                *(float4*)&out[(xbase + h * 96 + wc) * 64 + og * 4] =
                    make_float4(vb[0][e], vb[1][e], vb[2][e], vb[3][e]);
            }
        }
    }
}

// ---------------- launch -----------------------------------------------------
extern "C" void kernel_launch(void* const* d_in, const int* in_sizes, int n_in,
                              void* d_out, int out_size) {
    const float* x        = (const float*)d_in[0];
    const float* se_w1    = (const float*)d_in[1];
    const float* se_b1    = (const float*)d_in[2];
    const float* se_w2    = (const float*)d_in[3];
    const float* se_b2    = (const float*)d_in[4];
    const float* dc_w     = (const float*)d_in[5];
    const float* dc_b     = (const float*)d_in[6];
    const float* l1_w     = (const float*)d_in[7];
    const float* l1_b     = (const float*)d_in[8];
    const float* l2_w     = (const float*)d_in[9];
    const float* l2_b     = (const float*)d_in[10];
    const float* gkf_w    = (const float*)d_in[11];
    const float* gkf_b    = (const float*)d_in[12];
    const float* fu_proj_w = (const float*)d_in[13];
    const float* fu_proj_b = (const float*)d_in[14];
    const float* fu_fc1_w = (const float*)d_in[15];
    const float* fu_fc1_b = (const float*)d_in[16];
    const float* fu_fc2_w = (const float*)d_in[17];
    const float* fu_fc2_b = (const float*)d_in[18];
    const float* fu_po_w  = (const float*)d_in[19];
    const float* fu_po_b  = (const float*)d_in[20];
    const float* po_w     = (const float*)d_in[21];
    const float* po_b     = (const float*)d_in[22];
    float* out = (float*)d_out;

    cudaFuncSetAttribute(k2_kernel, cudaFuncAttributeMaxDynamicSharedMemorySize, 56000);
    cudaFuncSetAttribute(k3_kernel, cudaFuncAttributeMaxDynamicSharedMemorySize,
                         K3_SMEM_FLOATS * 4);

    dim3 pgrid(9, 128);
    pool_kernel<<<pgrid, 256>>>(x);
    k2_kernel<<<32, 256, 54352>>>(se_w1, se_b1, se_w2, se_b2, dc_w, dc_b,
                                  l1_w, l1_b, l2_w, l2_b, gkf_w, gkf_b,
                                  fu_proj_w, fu_proj_b, fu_fc1_w, fu_fc1_b,
                                  fu_fc2_w, fu_fc2_b, fu_po_w, fu_po_b);
    dim3 grid(6, 6, 32);
    k3_kernel<<<grid, 256, K3_SMEM_FLOATS * 4>>>(x, po_w, po_b, out);
}